// round 14
// baseline (speedup 1.0000x reference)
#include <cuda_runtime.h>
#include <cuda_fp16.h>
#include <math.h>
#include <stdint.h>

#define NMAX 100000

// Scratch (module-static):
__device__ float4 g_qn[NMAX * 2];      // per-node: [0]=frame quaternion, [1]=(X, valid)
__device__ unsigned long long gBfrag[1536]; // B fragments [s(3)][j(16)][lane(32)]

struct F3 { float x, y, z; };
__device__ __forceinline__ F3 mk3(float a, float b, float c) { F3 r; r.x = a; r.y = b; r.z = c; return r; }
__device__ __forceinline__ F3 sub3(F3 a, F3 b) { return mk3(a.x - b.x, a.y - b.y, a.z - b.z); }
__device__ __forceinline__ float dot3(F3 a, F3 b) { return a.x * b.x + a.y * b.y + a.z * b.z; }
__device__ __forceinline__ F3 cross3(F3 a, F3 b) {
    return mk3(a.y * b.z - a.z * b.y, a.z * b.x - a.x * b.z, a.x * b.y - a.y * b.x);
}
__device__ __forceinline__ F3 nrm3(F3 a) {
    float n = sqrtf(dot3(a, a));
    float s = 1.0f / fmaxf(n, 1e-12f);
    return mk3(a.x * s, a.y * s, a.z * s);
}
__device__ __forceinline__ float signf_(float x) { return (float)((x > 0.0f) - (x < 0.0f)); }

__device__ __forceinline__ uint32_t smem_u32(const void* p) {
    uint32_t a;
    asm("{ .reg .u64 t; cvta.to.shared.u64 t, %1; cvt.u32.u64 %0, t; }" : "=r"(a) : "l"(p));
    return a;
}
__device__ __forceinline__ void mma16816h(float* c, uint32_t a0, uint32_t a1, uint32_t a2, uint32_t a3,
                                          uint32_t b0, uint32_t b1) {
    asm volatile(
        "mma.sync.aligned.m16n8k16.row.col.f32.f16.f16.f32 "
        "{%0,%1,%2,%3}, {%4,%5,%6,%7}, {%8,%9}, {%0,%1,%2,%3};"
        : "+f"(c[0]), "+f"(c[1]), "+f"(c[2]), "+f"(c[3])
        : "r"(a0), "r"(a1), "r"(a2), "r"(a3), "r"(b0), "r"(b1));
}
__device__ __forceinline__ void ldmatrix_x4(uint32_t& a0, uint32_t& a1, uint32_t& a2, uint32_t& a3, uint32_t addr) {
    asm volatile("ldmatrix.sync.aligned.m8n8.x4.shared.b16 {%0,%1,%2,%3}, [%4];"
                 : "=r"(a0), "=r"(a1), "=r"(a2), "=r"(a3) : "r"(addr));
}
__device__ __forceinline__ float h16rt(float x) {   // round-trip through fp16
    return __half2float(__float2half(x));
}
__device__ __forceinline__ uint32_t packh2(float a, float b) {
    __half2 p = __floats2half2_rn(a, b);
    return *reinterpret_cast<uint32_t*>(&p);
}
// pack {f16(x), x - f16(x)} into one uint32 (interleaved hi/lo column pair)
__device__ __forceinline__ uint32_t hilo(float x) {
    float h = h16rt(x);
    return packh2(h, x - h);
}

// ---------------------------------------------------------------------------
// Fused node kernel: per-thread geometry -> smem; warp-per-node matmul + LN.
// Block 0 additionally builds the fp16 B fragments for the edge GEMM.
// ---------------------------------------------------------------------------
__global__ void __launch_bounds__(256)
k_node(const float* __restrict__ X, const int* __restrict__ batch, int N,
       const float* __restrict__ Wn, const float* __restrict__ bn,
       const float* __restrict__ gn, const float* __restrict__ bet,
       const float* __restrict__ We, const float* __restrict__ be,
       float* __restrict__ hV)
{
    __shared__ float4 s_nf[256];

    int tid = threadIdx.x, w = tid >> 5, lane = tid & 31;
    int base = blockIdx.x * 256;
    int i = base + tid;

    // ---- block 0: build B fragments (K'=48, interleaved hi/lo K-layout) ----
    // K row r: r<46 -> f16(W[r>>1]); r=46 -> f16(b); r=47 -> b - f16(b).
    if (blockIdx.x == 0) {
#pragma unroll
        for (int u = 0; u < 6; u++) {
            int idx = tid + 256 * u;   // 6*256 = 1536
            int fl = idx & 31, j = (idx >> 5) & 15, s = idx >> 9;
            int fgid = fl >> 2, ftig = fl & 3;
            int fw = j >> 2, fjj = j & 3;
            int n = 32 * fw + 8 * (fgid >> 1) + 2 * fjj + (fgid & 1);
            auto wv = [&](int r) -> float {
                if (r < 46)  return h16rt(We[(r >> 1) * 128 + n]);
                if (r == 46) return h16rt(be[n]);
                if (r == 47) { float x = be[n]; return x - h16rt(x); }
                return 0.0f;
            };
            int k0 = 16 * s + 2 * ftig;
            uint32_t b0 = packh2(wv(k0),     wv(k0 + 1));
            uint32_t b1 = packh2(wv(k0 + 8), wv(k0 + 9));
            gBfrag[idx] = ((unsigned long long)b1 << 32) | b0;
        }
    }

    if (i < N) {
        auto ldx = [&](int j) -> F3 {
            j = j < 0 ? 0 : (j > N - 1 ? N - 1 : j);
            return mk3(X[3 * j], X[3 * j + 1], X[3 * j + 2]);
        };
        F3 xm1 = ldx(i - 1), x0 = ldx(i), xp1 = ldx(i + 1), xp2 = ldx(i + 2);

        int bi   = (i > 0)     && (batch[i] != batch[i - 1]);
        int bip1 = (i + 1 < N) && (batch[i + 1] != batch[i]);
        int bip2 = (i + 2 < N) && (batch[i + 2] != batch[i + 1]);
        bool bad_a = bi || bip1 || (i == 0) || (i == N - 1);
        bool bad_d = bi || bip1 || bip2 || (i == 0) || (i >= N - 2);

        F3 Um = nrm3(sub3(x0,  xm1));
        F3 Uc = nrm3(sub3(xp1, x0));
        F3 Up = nrm3(sub3(xp2, xp1));

        F3 c1 = nrm3(cross3(Um, Uc));
        F3 c2 = nrm3(cross3(Uc, Up));
        float cosd = fminf(fmaxf(dot3(c1, c2), -1.0f + 1e-6f), 1.0f - 1e-6f);
        float sg = signf_(dot3(c2, Um));
        float sdih = sg * sqrtf(fmaxf(1.0f - cosd * cosd, 0.0f));
        float cdih = (sg == 0.0f) ? 1.0f : cosd;

        F3 d0 = nrm3(sub3(xm1, x0));
        F3 d1 = nrm3(sub3(xp1, x0));
        float cosa = dot3(d0, d1);
        float sina = sqrtf(1.0f - cosa * cosa + 1e-6f);

        float4 nf;
        nf.x = bad_d ? 0.0f : sdih;
        nf.y = bad_d ? 0.0f : cdih;
        nf.z = bad_a ? 0.0f : sina;
        nf.w = bad_a ? 0.0f : cosa;
        s_nf[tid] = nf;

        // Local frame Q = [bv nv cv]; convert to quaternion (Shepperd).
        F3 bv = nrm3(sub3(Um, Uc));
        F3 nv = nrm3(cross3(Um, Uc));
        F3 cv = cross3(bv, nv);

        float qx = 0.0f, qy = 0.0f, qz = 0.0f, qw = 1.0f;
        if (!bad_a) {
            float m00 = bv.x, m10 = bv.y, m20 = bv.z;
            float m01 = nv.x, m11 = nv.y, m21 = nv.z;
            float m02 = cv.x, m12 = cv.y, m22 = cv.z;
            float tr = m00 + m11 + m22;
            if (tr > 0.0f) {
                float S = fmaxf(sqrtf(fmaxf(tr + 1.0f, 0.0f)) * 2.0f, 1e-20f);
                qw = 0.25f * S;
                qx = (m21 - m12) / S;
                qy = (m02 - m20) / S;
                qz = (m10 - m01) / S;
            } else if (m00 >= m11 && m00 >= m22) {
                float S = fmaxf(sqrtf(fmaxf(1.0f + m00 - m11 - m22, 0.0f)) * 2.0f, 1e-20f);
                qw = (m21 - m12) / S;
                qx = 0.25f * S;
                qy = (m01 + m10) / S;
                qz = (m02 + m20) / S;
            } else if (m11 >= m22) {
                float S = fmaxf(sqrtf(fmaxf(1.0f + m11 - m00 - m22, 0.0f)) * 2.0f, 1e-20f);
                qw = (m02 - m20) / S;
                qx = (m01 + m10) / S;
                qy = 0.25f * S;
                qz = (m12 + m21) / S;
            } else {
                float S = fmaxf(sqrtf(fmaxf(1.0f + m22 - m00 - m11, 0.0f)) * 2.0f, 1e-20f);
                qw = (m10 - m01) / S;
                qx = (m02 + m20) / S;
                qy = (m12 + m21) / S;
                qz = 0.25f * S;
            }
            float nq = rsqrtf(fmaxf(qx * qx + qy * qy + qz * qz + qw * qw, 1e-24f));
            qx *= nq; qy *= nq; qz *= nq; qw *= nq;
        }
        g_qn[i * 2 + 0] = make_float4(qx, qy, qz, qw);
        g_qn[i * 2 + 1] = make_float4(x0.x, x0.y, x0.z, bad_a ? 0.0f : 1.0f);
    } else {
        s_nf[tid] = make_float4(0.f, 0.f, 0.f, 0.f);
    }
    __syncthreads();

    // warp-per-node output: warp w handles local nodes 32w .. 32w+31
    int c = 4 * lane;
    float4 w0 = *reinterpret_cast<const float4*>(Wn + 0 * 128 + c);
    float4 w1 = *reinterpret_cast<const float4*>(Wn + 1 * 128 + c);
    float4 w2 = *reinterpret_cast<const float4*>(Wn + 2 * 128 + c);
    float4 w3 = *reinterpret_cast<const float4*>(Wn + 3 * 128 + c);
    float4 bb = *reinterpret_cast<const float4*>(bn + c);
    float4 gg = *reinterpret_cast<const float4*>(gn + c);
    float4 bt = *reinterpret_cast<const float4*>(bet + c);

#pragma unroll 1
    for (int it = 0; it < 32; it++) {
        int gw = base + 32 * w + it;
        if (gw >= N) break;
        float4 f = s_nf[32 * w + it];
        float4 a;
        a.x = bb.x + f.x * w0.x + f.y * w1.x + f.z * w2.x + f.w * w3.x;
        a.y = bb.y + f.x * w0.y + f.y * w1.y + f.z * w2.y + f.w * w3.y;
        a.z = bb.z + f.x * w0.z + f.y * w1.z + f.z * w2.z + f.w * w3.z;
        a.w = bb.w + f.x * w0.w + f.y * w1.w + f.z * w2.w + f.w * w3.w;

        float s1 = a.x + a.y + a.z + a.w;
        float s2 = a.x * a.x + a.y * a.y + a.z * a.z + a.w * a.w;
#pragma unroll
        for (int o = 16; o > 0; o >>= 1) {
            s1 += __shfl_xor_sync(0xffffffffu, s1, o);
            s2 += __shfl_xor_sync(0xffffffffu, s2, o);
        }
        float mean = s1 * (1.0f / 128.0f);
        float var  = fmaxf(s2 * (1.0f / 128.0f) - mean * mean, 0.0f);
        float inv  = rsqrtf(var + 1e-5f);
        float4 o4;
        o4.x = (a.x - mean) * inv * gg.x + bt.x;
        o4.y = (a.y - mean) * inv * gg.y + bt.y;
        o4.z = (a.z - mean) * inv * gg.z + bt.z;
        o4.w = (a.w - mean) * inv * gg.w + bt.w;
        __stcs(reinterpret_cast<float4*>(hV + (size_t)gw * 128 + c), o4);
    }
}

// ---------------------------------------------------------------------------
// FUSED edge features (quaternion path) + fp16 tensor GEMM + LN.
// Block = 128 threads = 4 warps; tile = 128 edges; K' = 48 (3 k-steps).
// LN params (g, beta) live in SMEM to keep phase-2 register count <= 72.
// ---------------------------------------------------------------------------
__global__ void __launch_bounds__(128, 7)
k_edge_fused(const int* __restrict__ ei, int E,
             const float* __restrict__ ge, const float* __restrict__ bet,
             float* __restrict__ hE)
{
    __shared__ __half A_img[128 * 56];   // stride 56 f16 = 112 B (conflict-free)
    __shared__ float2 red[2][16][5];
    __shared__ float2 sGB[128];          // (g, beta) per output column

    int tid = threadIdx.x, w = tid >> 5, lane = tid & 31;
    int gid = lane >> 2, tig = lane & 3;
    int base = blockIdx.x * 128;

    sGB[tid] = make_float2(ge[tid], bet[tid]);

    // ---- Phase 1: per-thread edge features, streaming hi/lo packs ----
    {
        int e = base + tid;
        uint4* Av = reinterpret_cast<uint4*>(A_img + tid * 56);
        if (e < E) {
            int s = __ldg(ei + e);
            int t = __ldg(ei + E + e);

            float4 qt = g_qn[2 * t], xt = g_qn[2 * t + 1];
            float4 qs = g_qn[2 * s], xs = g_qn[2 * s + 1];

            float dvx = xs.x - xt.x, dvy = xs.y - xt.y, dvz = xs.z - xt.z;
            float d2   = dvx * dvx + dvy * dvy + dvz * dvz;
            float dist = sqrtf(d2 + 1e-6f);
            float rinv = 1.0f / fmaxf(sqrtf(d2), 1e-12f);
            float dhx = dvx * rinv, dhy = dvy * rinv, dhz = dvz * rinv;

            // q_rel = conj(q_t) * q_s  -> features f0..f3 -> cols 0..7
            {
                float rw = qt.w * qs.w + qt.x * qs.x + qt.y * qs.y + qt.z * qs.z;
                float rx = qt.w * qs.x - qs.w * qt.x - (qt.y * qs.z - qt.z * qs.y);
                float ry = qt.w * qs.y - qs.w * qt.y - (qt.z * qs.x - qt.x * qs.z);
                float rz = qt.w * qs.z - qs.w * qt.z - (qt.x * qs.y - qt.y * qs.x);
                float sgnw = signf_(rw);
                float qn2 = rx * rx + ry * ry + rz * rz + rw * rw;
                float vm = (xt.w * xs.w) * sgnw / fmaxf(sqrtf(qn2), 1e-12f);
                Av[0] = make_uint4(hilo(rx * vm), hilo(ry * vm), hilo(rz * vm), hilo(rw * vm));
            }

            // RBF f4..f19 -> cols 8..39, streamed 4 at a time
#pragma unroll
            for (int g = 0; g < 4; g++) {
                uint32_t au[4];
#pragma unroll
                for (int h = 0; h < 4; h++) {
                    float mu = (float)(4 * g + h) * (20.0f / 15.0f);
                    float tt = (dist - mu) * 0.8f;
                    au[h] = hilo(__expf(-tt * tt));
                }
                Av[1 + g] = make_uint4(au[0], au[1], au[2], au[3]);
            }

            // direct f20..f22 -> cols 40..45; bias ones -> cols 46..47
            {
                float ax = qt.x, ay = qt.y, az = qt.z, aw = qt.w;
                float t1x = ay * dhz - az * dhy;
                float t1y = az * dhx - ax * dhz;
                float t1z = ax * dhy - ay * dhx;
                float ux = ay * t1z - az * t1y;
                float uy = az * t1x - ax * t1z;
                float uz = ax * t1y - ay * t1x;
                float d0 = (dhx - 2.0f * aw * t1x + 2.0f * ux) * xt.w;
                float d1 = (dhy - 2.0f * aw * t1y + 2.0f * uy) * xt.w;
                float d2d = (dhz - 2.0f * aw * t1z + 2.0f * uz) * xt.w;
                Av[5] = make_uint4(hilo(d0), hilo(d1), hilo(d2d), packh2(1.0f, 1.0f));
            }
        } else {
            uint4 z = make_uint4(0u, 0u, 0u, 0u);
#pragma unroll
            for (int g = 0; g < 6; g++) Av[g] = z;
        }
    }
    __syncthreads();

    // ---- B fragments (24 regs) ----
    uint32_t B0[3][4], B1[3][4];
#pragma unroll
    for (int s = 0; s < 3; s++)
#pragma unroll
        for (int jj = 0; jj < 4; jj++) {
            unsigned long long v = gBfrag[(s * 16 + (w * 4 + jj)) * 32 + lane];
            B0[s][jj] = (uint32_t)v;
            B1[s][jj] = (uint32_t)(v >> 32);
        }

    uint32_t aBase = smem_u32(A_img)
                   + ((lane & 7) + ((lane & 8) ? 8 : 0)) * 112
                   + ((lane & 16) ? 16 : 0);
    int colb = 32 * w + 8 * tig;   // this lane's 8 contiguous output columns

    // ---- Phase 2: 8 row-groups of 16 edges, one sync each ----
#pragma unroll 1
    for (int rg = 0; rg < 8; rg++) {
        int buf = rg & 1;
        float C[4][4];
#pragma unroll
        for (int jj = 0; jj < 4; jj++)
#pragma unroll
            for (int q = 0; q < 4; q++) C[jj][q] = 0.0f;

        uint32_t aAddr = aBase + rg * (16 * 112);
#pragma unroll
        for (int s = 0; s < 3; s++) {
            uint32_t a0, a1, a2, a3;
            ldmatrix_x4(a0, a1, a2, a3, aAddr + s * 32);
#pragma unroll
            for (int jj = 0; jj < 4; jj++)
                mma16816h(C[jj], a0, a1, a2, a3, B0[s][jj], B1[s][jj]);
        }

        float s1A = 0.f, s2A = 0.f, s1B = 0.f, s2B = 0.f;
#pragma unroll
        for (int jj = 0; jj < 4; jj++) {
            s1A += C[jj][0] + C[jj][1];
            s2A += C[jj][0] * C[jj][0] + C[jj][1] * C[jj][1];
            s1B += C[jj][2] + C[jj][3];
            s2B += C[jj][2] * C[jj][2] + C[jj][3] * C[jj][3];
        }
#pragma unroll
        for (int o = 1; o <= 2; o <<= 1) {
            s1A += __shfl_xor_sync(0xffffffffu, s1A, o);
            s2A += __shfl_xor_sync(0xffffffffu, s2A, o);
            s1B += __shfl_xor_sync(0xffffffffu, s1B, o);
            s2B += __shfl_xor_sync(0xffffffffu, s2B, o);
        }
        if (tig == 0) {
            red[buf][gid][w]     = make_float2(s1A, s2A);
            red[buf][gid + 8][w] = make_float2(s1B, s2B);
        }
        __syncthreads();

        float u1 = 0.f, u2 = 0.f, v1 = 0.f, v2 = 0.f;
#pragma unroll
        for (int ww = 0; ww < 4; ww++) {
            float2 a = red[buf][gid][ww];
            float2 b = red[buf][gid + 8][ww];
            u1 += a.x; u2 += a.y;
            v1 += b.x; v2 += b.y;
        }
        float meanA = u1 * (1.0f / 128.0f);
        float invA  = rsqrtf(fmaxf(u2 * (1.0f / 128.0f) - meanA * meanA, 0.0f) + 1e-5f);
        float meanB = v1 * (1.0f / 128.0f);
        float invB  = rsqrtf(fmaxf(v2 * (1.0f / 128.0f) - meanB * meanB, 0.0f) + 1e-5f);

        int eA = base + rg * 16 + gid, eB = eA + 8;
        if (eA < E) {
            float4 lo, hi;
            float2 g0 = sGB[colb + 0], g1 = sGB[colb + 1], g2 = sGB[colb + 2], g3 = sGB[colb + 3];
            float2 g4 = sGB[colb + 4], g5 = sGB[colb + 5], g6 = sGB[colb + 6], g7 = sGB[colb + 7];
            lo.x = (C[0][0] - meanA) * invA * g0.x + g0.y;
            lo.y = (C[0][1] - meanA) * invA * g1.x + g1.y;
            lo.z = (C[1][0] - meanA) * invA * g2.x + g2.y;
            lo.w = (C[1][1] - meanA) * invA * g3.x + g3.y;
            hi.x = (C[2][0] - meanA) * invA * g4.x + g4.y;
            hi.y = (C[2][1] - meanA) * invA * g5.x + g5.y;
            hi.z = (C[3][0] - meanA) * invA * g6.x + g6.y;
            hi.w = (C[3][1] - meanA) * invA * g7.x + g7.y;
            float* dst = hE + (size_t)eA * 128 + colb;
            __stcs(reinterpret_cast<float4*>(dst),     lo);
            __stcs(reinterpret_cast<float4*>(dst + 4), hi);
        }
        if (eB < E) {
            float4 lo, hi;
            float2 g0 = sGB[colb + 0], g1 = sGB[colb + 1], g2 = sGB[colb + 2], g3 = sGB[colb + 3];
            float2 g4 = sGB[colb + 4], g5 = sGB[colb + 5], g6 = sGB[colb + 6], g7 = sGB[colb + 7];
            lo.x = (C[0][2] - meanB) * invB * g0.x + g0.y;
            lo.y = (C[0][3] - meanB) * invB * g1.x + g1.y;
            lo.z = (C[1][2] - meanB) * invB * g2.x + g2.y;
            lo.w = (C[1][3] - meanB) * invB * g3.x + g3.y;
            hi.x = (C[2][2] - meanB) * invB * g4.x + g4.y;
            hi.y = (C[2][3] - meanB) * invB * g5.x + g5.y;
            hi.z = (C[3][2] - meanB) * invB * g6.x + g6.y;
            hi.w = (C[3][3] - meanB) * invB * g7.x + g7.y;
            float* dst = hE + (size_t)eB * 128 + colb;
            __stcs(reinterpret_cast<float4*>(dst),     lo);
            __stcs(reinterpret_cast<float4*>(dst + 4), hi);
        }
    }
}

// ---------------------------------------------------------------------------
extern "C" void kernel_launch(void* const* d_in, const int* in_sizes, int n_in,
                              void* d_out, int out_size)
{
    const float* X    = (const float*)d_in[0];
    const int*   bat  = (const int*)d_in[1];
    const int*   ei   = (const int*)d_in[2];
    const float* Wn   = (const float*)d_in[3];
    const float* bn   = (const float*)d_in[4];
    const float* gn   = (const float*)d_in[5];
    const float* btn  = (const float*)d_in[6];
    const float* We   = (const float*)d_in[7];
    const float* be   = (const float*)d_in[8];
    const float* ge   = (const float*)d_in[9];
    const float* bte  = (const float*)d_in[10];

    int N = in_sizes[0] / 3;
    int E = in_sizes[2] / 2;

    float* hV = (float*)d_out;
    float* hE = hV + (size_t)N * 128;

    k_node<<<(N + 255) / 256, 256>>>(X, bat, N, Wn, bn, gn, btn, We, be, hV);
    k_edge_fused<<<(E + 127) / 128, 128>>>(ei, E, ge, bte, hE);
}

// round 15
// speedup vs baseline: 1.2719x; 1.2719x over previous
#include <cuda_runtime.h>
#include <cuda_fp16.h>
#include <math.h>
#include <stdint.h>

#define NMAX 100000

// Scratch (module-static):
__device__ float4 g_qn[NMAX * 2];      // per-node: [0]=frame quaternion, [1]=(X, valid)
__device__ unsigned long long gBfrag[1536]; // B fragments [s(3)][j(16)][lane(32)]

struct F3 { float x, y, z; };
__device__ __forceinline__ F3 mk3(float a, float b, float c) { F3 r; r.x = a; r.y = b; r.z = c; return r; }
__device__ __forceinline__ F3 sub3(F3 a, F3 b) { return mk3(a.x - b.x, a.y - b.y, a.z - b.z); }
__device__ __forceinline__ float dot3(F3 a, F3 b) { return a.x * b.x + a.y * b.y + a.z * b.z; }
__device__ __forceinline__ F3 cross3(F3 a, F3 b) {
    return mk3(a.y * b.z - a.z * b.y, a.z * b.x - a.x * b.z, a.x * b.y - a.y * b.x);
}
__device__ __forceinline__ F3 nrm3(F3 a) {
    float n = sqrtf(dot3(a, a));
    float s = 1.0f / fmaxf(n, 1e-12f);
    return mk3(a.x * s, a.y * s, a.z * s);
}
__device__ __forceinline__ float signf_(float x) { return (float)((x > 0.0f) - (x < 0.0f)); }

__device__ __forceinline__ uint32_t smem_u32(const void* p) {
    uint32_t a;
    asm("{ .reg .u64 t; cvta.to.shared.u64 t, %1; cvt.u32.u64 %0, t; }" : "=r"(a) : "l"(p));
    return a;
}
__device__ __forceinline__ void mma16816h(float* c, uint32_t a0, uint32_t a1, uint32_t a2, uint32_t a3,
                                          uint32_t b0, uint32_t b1) {
    asm volatile(
        "mma.sync.aligned.m16n8k16.row.col.f32.f16.f16.f32 "
        "{%0,%1,%2,%3}, {%4,%5,%6,%7}, {%8,%9}, {%0,%1,%2,%3};"
        : "+f"(c[0]), "+f"(c[1]), "+f"(c[2]), "+f"(c[3])
        : "r"(a0), "r"(a1), "r"(a2), "r"(a3), "r"(b0), "r"(b1));
}
__device__ __forceinline__ void ldmatrix_x4(uint32_t& a0, uint32_t& a1, uint32_t& a2, uint32_t& a3, uint32_t addr) {
    asm volatile("ldmatrix.sync.aligned.m8n8.x4.shared.b16 {%0,%1,%2,%3}, [%4];"
                 : "=r"(a0), "=r"(a1), "=r"(a2), "=r"(a3) : "r"(addr));
}
__device__ __forceinline__ float h16rt(float x) {   // round-trip through fp16
    return __half2float(__float2half(x));
}
__device__ __forceinline__ uint32_t packh2(float a, float b) {
    __half2 p = __floats2half2_rn(a, b);
    return *reinterpret_cast<uint32_t*>(&p);
}
// pack {f16(x), x - f16(x)} into one uint32 (interleaved hi/lo column pair)
__device__ __forceinline__ uint32_t hilo(float x) {
    float h = h16rt(x);
    return packh2(h, x - h);
}

// ---------------------------------------------------------------------------
// Fused node kernel: per-thread geometry -> smem; warp-per-node matmul + LN.
// Block 0 additionally builds the fp16 B fragments for the edge GEMM.
// ---------------------------------------------------------------------------
__global__ void __launch_bounds__(256)
k_node(const float* __restrict__ X, const int* __restrict__ batch, int N,
       const float* __restrict__ Wn, const float* __restrict__ bn,
       const float* __restrict__ gn, const float* __restrict__ bet,
       const float* __restrict__ We, const float* __restrict__ be,
       float* __restrict__ hV)
{
    __shared__ float4 s_nf[256];

    int tid = threadIdx.x, w = tid >> 5, lane = tid & 31;
    int base = blockIdx.x * 256;
    int i = base + tid;

    // ---- block 0: build B fragments (K'=48, interleaved hi/lo K-layout) ----
    // K row r: r<46 -> f16(W[r>>1]); r=46 -> f16(b); r=47 -> b - f16(b).
    if (blockIdx.x == 0) {
#pragma unroll
        for (int u = 0; u < 6; u++) {
            int idx = tid + 256 * u;   // 6*256 = 1536
            int fl = idx & 31, j = (idx >> 5) & 15, s = idx >> 9;
            int fgid = fl >> 2, ftig = fl & 3;
            int fw = j >> 2, fjj = j & 3;
            int n = 32 * fw + 8 * (fgid >> 1) + 2 * fjj + (fgid & 1);
            auto wv = [&](int r) -> float {
                if (r < 46)  return h16rt(We[(r >> 1) * 128 + n]);
                if (r == 46) return h16rt(be[n]);
                if (r == 47) { float x = be[n]; return x - h16rt(x); }
                return 0.0f;
            };
            int k0 = 16 * s + 2 * ftig;
            uint32_t b0 = packh2(wv(k0),     wv(k0 + 1));
            uint32_t b1 = packh2(wv(k0 + 8), wv(k0 + 9));
            gBfrag[idx] = ((unsigned long long)b1 << 32) | b0;
        }
    }

    if (i < N) {
        auto ldx = [&](int j) -> F3 {
            j = j < 0 ? 0 : (j > N - 1 ? N - 1 : j);
            return mk3(X[3 * j], X[3 * j + 1], X[3 * j + 2]);
        };
        F3 xm1 = ldx(i - 1), x0 = ldx(i), xp1 = ldx(i + 1), xp2 = ldx(i + 2);

        int bi   = (i > 0)     && (batch[i] != batch[i - 1]);
        int bip1 = (i + 1 < N) && (batch[i + 1] != batch[i]);
        int bip2 = (i + 2 < N) && (batch[i + 2] != batch[i + 1]);
        bool bad_a = bi || bip1 || (i == 0) || (i == N - 1);
        bool bad_d = bi || bip1 || bip2 || (i == 0) || (i >= N - 2);

        F3 Um = nrm3(sub3(x0,  xm1));
        F3 Uc = nrm3(sub3(xp1, x0));
        F3 Up = nrm3(sub3(xp2, xp1));

        F3 c1 = nrm3(cross3(Um, Uc));
        F3 c2 = nrm3(cross3(Uc, Up));
        float cosd = fminf(fmaxf(dot3(c1, c2), -1.0f + 1e-6f), 1.0f - 1e-6f);
        float sg = signf_(dot3(c2, Um));
        float sdih = sg * sqrtf(fmaxf(1.0f - cosd * cosd, 0.0f));
        float cdih = (sg == 0.0f) ? 1.0f : cosd;

        F3 d0 = nrm3(sub3(xm1, x0));
        F3 d1 = nrm3(sub3(xp1, x0));
        float cosa = dot3(d0, d1);
        float sina = sqrtf(1.0f - cosa * cosa + 1e-6f);

        float4 nf;
        nf.x = bad_d ? 0.0f : sdih;
        nf.y = bad_d ? 0.0f : cdih;
        nf.z = bad_a ? 0.0f : sina;
        nf.w = bad_a ? 0.0f : cosa;
        s_nf[tid] = nf;

        // Local frame Q = [bv nv cv]; convert to quaternion (Shepperd).
        F3 bv = nrm3(sub3(Um, Uc));
        F3 nv = nrm3(cross3(Um, Uc));
        F3 cv = cross3(bv, nv);

        float qx = 0.0f, qy = 0.0f, qz = 0.0f, qw = 1.0f;
        if (!bad_a) {
            float m00 = bv.x, m10 = bv.y, m20 = bv.z;
            float m01 = nv.x, m11 = nv.y, m21 = nv.z;
            float m02 = cv.x, m12 = cv.y, m22 = cv.z;
            float tr = m00 + m11 + m22;
            if (tr > 0.0f) {
                float S = fmaxf(sqrtf(fmaxf(tr + 1.0f, 0.0f)) * 2.0f, 1e-20f);
                qw = 0.25f * S;
                qx = (m21 - m12) / S;
                qy = (m02 - m20) / S;
                qz = (m10 - m01) / S;
            } else if (m00 >= m11 && m00 >= m22) {
                float S = fmaxf(sqrtf(fmaxf(1.0f + m00 - m11 - m22, 0.0f)) * 2.0f, 1e-20f);
                qw = (m21 - m12) / S;
                qx = 0.25f * S;
                qy = (m01 + m10) / S;
                qz = (m02 + m20) / S;
            } else if (m11 >= m22) {
                float S = fmaxf(sqrtf(fmaxf(1.0f + m11 - m00 - m22, 0.0f)) * 2.0f, 1e-20f);
                qw = (m02 - m20) / S;
                qx = (m01 + m10) / S;
                qy = 0.25f * S;
                qz = (m12 + m21) / S;
            } else {
                float S = fmaxf(sqrtf(fmaxf(1.0f + m22 - m00 - m11, 0.0f)) * 2.0f, 1e-20f);
                qw = (m10 - m01) / S;
                qx = (m02 + m20) / S;
                qy = (m12 + m21) / S;
                qz = 0.25f * S;
            }
            float nq = rsqrtf(fmaxf(qx * qx + qy * qy + qz * qz + qw * qw, 1e-24f));
            qx *= nq; qy *= nq; qz *= nq; qw *= nq;
        }
        g_qn[i * 2 + 0] = make_float4(qx, qy, qz, qw);
        g_qn[i * 2 + 1] = make_float4(x0.x, x0.y, x0.z, bad_a ? 0.0f : 1.0f);
    } else {
        s_nf[tid] = make_float4(0.f, 0.f, 0.f, 0.f);
    }
    __syncthreads();

    // warp-per-node output: warp w handles local nodes 32w .. 32w+31
    int c = 4 * lane;
    float4 w0 = *reinterpret_cast<const float4*>(Wn + 0 * 128 + c);
    float4 w1 = *reinterpret_cast<const float4*>(Wn + 1 * 128 + c);
    float4 w2 = *reinterpret_cast<const float4*>(Wn + 2 * 128 + c);
    float4 w3 = *reinterpret_cast<const float4*>(Wn + 3 * 128 + c);
    float4 bb = *reinterpret_cast<const float4*>(bn + c);
    float4 gg = *reinterpret_cast<const float4*>(gn + c);
    float4 bt = *reinterpret_cast<const float4*>(bet + c);

#pragma unroll 1
    for (int it = 0; it < 32; it++) {
        int gw = base + 32 * w + it;
        if (gw >= N) break;
        float4 f = s_nf[32 * w + it];
        float4 a;
        a.x = bb.x + f.x * w0.x + f.y * w1.x + f.z * w2.x + f.w * w3.x;
        a.y = bb.y + f.x * w0.y + f.y * w1.y + f.z * w2.y + f.w * w3.y;
        a.z = bb.z + f.x * w0.z + f.y * w1.z + f.z * w2.z + f.w * w3.z;
        a.w = bb.w + f.x * w0.w + f.y * w1.w + f.z * w2.w + f.w * w3.w;

        float s1 = a.x + a.y + a.z + a.w;
        float s2 = a.x * a.x + a.y * a.y + a.z * a.z + a.w * a.w;
#pragma unroll
        for (int o = 16; o > 0; o >>= 1) {
            s1 += __shfl_xor_sync(0xffffffffu, s1, o);
            s2 += __shfl_xor_sync(0xffffffffu, s2, o);
        }
        float mean = s1 * (1.0f / 128.0f);
        float var  = fmaxf(s2 * (1.0f / 128.0f) - mean * mean, 0.0f);
        float inv  = rsqrtf(var + 1e-5f);
        float4 o4;
        o4.x = (a.x - mean) * inv * gg.x + bt.x;
        o4.y = (a.y - mean) * inv * gg.y + bt.y;
        o4.z = (a.z - mean) * inv * gg.z + bt.z;
        o4.w = (a.w - mean) * inv * gg.w + bt.w;
        __stcs(reinterpret_cast<float4*>(hV + (size_t)gw * 128 + c), o4);
    }
}

// ---------------------------------------------------------------------------
// FUSED edge features (quaternion path) + fp16 tensor GEMM + LN.
// Block = 128 threads = 4 warps; tile = 128 edges; K' = 48 (3 k-steps).
// A row (interleaved): col 2k = f16(f[k]), col 2k+1 = f[k]-f16(f[k]);
// cols 46,47 = 1. LN params register-resident (validated optimum).
// ---------------------------------------------------------------------------
__global__ void __launch_bounds__(128, 6)
k_edge_fused(const int* __restrict__ ei, int E,
             const float* __restrict__ ge, const float* __restrict__ bet,
             float* __restrict__ hE)
{
    __shared__ __half A_img[128 * 56];   // stride 56 f16 = 112 B (conflict-free)
    __shared__ float2 red[2][16][5];

    int tid = threadIdx.x, w = tid >> 5, lane = tid & 31;
    int gid = lane >> 2, tig = lane & 3;
    int base = blockIdx.x * 128;

    // ---- Phase 1: per-thread edge features, streaming hi/lo packs ----
    {
        int e = base + tid;
        uint4* Av = reinterpret_cast<uint4*>(A_img + tid * 56);
        if (e < E) {
            int s = __ldg(ei + e);
            int t = __ldg(ei + E + e);

            float4 qt = g_qn[2 * t], xt = g_qn[2 * t + 1];
            float4 qs = g_qn[2 * s], xs = g_qn[2 * s + 1];

            float dvx = xs.x - xt.x, dvy = xs.y - xt.y, dvz = xs.z - xt.z;
            float d2   = dvx * dvx + dvy * dvy + dvz * dvz;
            float dist = sqrtf(d2 + 1e-6f);
            float rinv = 1.0f / fmaxf(sqrtf(d2), 1e-12f);
            float dhx = dvx * rinv, dhy = dvy * rinv, dhz = dvz * rinv;

            // q_rel = conj(q_t) * q_s  -> features f0..f3 -> cols 0..7
            {
                float rw = qt.w * qs.w + qt.x * qs.x + qt.y * qs.y + qt.z * qs.z;
                float rx = qt.w * qs.x - qs.w * qt.x - (qt.y * qs.z - qt.z * qs.y);
                float ry = qt.w * qs.y - qs.w * qt.y - (qt.z * qs.x - qt.x * qs.z);
                float rz = qt.w * qs.z - qs.w * qt.z - (qt.x * qs.y - qt.y * qs.x);
                float sgnw = signf_(rw);
                float qn2 = rx * rx + ry * ry + rz * rz + rw * rw;
                float vm = (xt.w * xs.w) * sgnw / fmaxf(sqrtf(qn2), 1e-12f);
                Av[0] = make_uint4(hilo(rx * vm), hilo(ry * vm), hilo(rz * vm), hilo(rw * vm));
            }

            // RBF f4..f19 -> cols 8..39, streamed 4 at a time
#pragma unroll
            for (int g = 0; g < 4; g++) {
                uint32_t au[4];
#pragma unroll
                for (int h = 0; h < 4; h++) {
                    float mu = (float)(4 * g + h) * (20.0f / 15.0f);
                    float tt = (dist - mu) * 0.8f;
                    au[h] = hilo(__expf(-tt * tt));
                }
                Av[1 + g] = make_uint4(au[0], au[1], au[2], au[3]);
            }

            // direct f20..f22 -> cols 40..45; bias ones -> cols 46..47
            {
                float ax = qt.x, ay = qt.y, az = qt.z, aw = qt.w;
                float t1x = ay * dhz - az * dhy;
                float t1y = az * dhx - ax * dhz;
                float t1z = ax * dhy - ay * dhx;
                float ux = ay * t1z - az * t1y;
                float uy = az * t1x - ax * t1z;
                float uz = ax * t1y - ay * t1x;
                float d0 = (dhx - 2.0f * aw * t1x + 2.0f * ux) * xt.w;
                float d1 = (dhy - 2.0f * aw * t1y + 2.0f * uy) * xt.w;
                float d2d = (dhz - 2.0f * aw * t1z + 2.0f * uz) * xt.w;
                Av[5] = make_uint4(hilo(d0), hilo(d1), hilo(d2d), packh2(1.0f, 1.0f));
            }
        } else {
            uint4 z = make_uint4(0u, 0u, 0u, 0u);
#pragma unroll
            for (int g = 0; g < 6; g++) Av[g] = z;
        }
    }
    __syncthreads();

    // ---- B fragments + LN params (registers — validated optimum) ----
    uint32_t B0[3][4], B1[3][4];
#pragma unroll
    for (int s = 0; s < 3; s++)
#pragma unroll
        for (int jj = 0; jj < 4; jj++) {
            unsigned long long v = gBfrag[(s * 16 + (w * 4 + jj)) * 32 + lane];
            B0[s][jj] = (uint32_t)v;
            B1[s][jj] = (uint32_t)(v >> 32);
        }
    float2 gg2[4], bt2[4];
#pragma unroll
    for (int jj = 0; jj < 4; jj++) {
        int colb = 32 * w + 8 * tig + 2 * jj;
        gg2[jj] = *reinterpret_cast<const float2*>(ge + colb);
        bt2[jj] = *reinterpret_cast<const float2*>(bet + colb);
    }

    uint32_t aBase = smem_u32(A_img)
                   + ((lane & 7) + ((lane & 8) ? 8 : 0)) * 112
                   + ((lane & 16) ? 16 : 0);

    // ---- Phase 2: 8 row-groups of 16 edges, one sync each ----
#pragma unroll 1
    for (int rg = 0; rg < 8; rg++) {
        int buf = rg & 1;
        float C[4][4];
#pragma unroll
        for (int jj = 0; jj < 4; jj++)
#pragma unroll
            for (int q = 0; q < 4; q++) C[jj][q] = 0.0f;

        uint32_t aAddr = aBase + rg * (16 * 112);
#pragma unroll
        for (int s = 0; s < 3; s++) {
            uint32_t a0, a1, a2, a3;
            ldmatrix_x4(a0, a1, a2, a3, aAddr + s * 32);
#pragma unroll
            for (int jj = 0; jj < 4; jj++)
                mma16816h(C[jj], a0, a1, a2, a3, B0[s][jj], B1[s][jj]);
        }

        float s1A = 0.f, s2A = 0.f, s1B = 0.f, s2B = 0.f;
#pragma unroll
        for (int jj = 0; jj < 4; jj++) {
            s1A += C[jj][0] + C[jj][1];
            s2A += C[jj][0] * C[jj][0] + C[jj][1] * C[jj][1];
            s1B += C[jj][2] + C[jj][3];
            s2B += C[jj][2] * C[jj][2] + C[jj][3] * C[jj][3];
        }
#pragma unroll
        for (int o = 1; o <= 2; o <<= 1) {
            s1A += __shfl_xor_sync(0xffffffffu, s1A, o);
            s2A += __shfl_xor_sync(0xffffffffu, s2A, o);
            s1B += __shfl_xor_sync(0xffffffffu, s1B, o);
            s2B += __shfl_xor_sync(0xffffffffu, s2B, o);
        }
        if (tig == 0) {
            red[buf][gid][w]     = make_float2(s1A, s2A);
            red[buf][gid + 8][w] = make_float2(s1B, s2B);
        }
        __syncthreads();

        float u1 = 0.f, u2 = 0.f, v1 = 0.f, v2 = 0.f;
#pragma unroll
        for (int ww = 0; ww < 4; ww++) {
            float2 a = red[buf][gid][ww];
            float2 b = red[buf][gid + 8][ww];
            u1 += a.x; u2 += a.y;
            v1 += b.x; v2 += b.y;
        }
        float meanA = u1 * (1.0f / 128.0f);
        float invA  = rsqrtf(fmaxf(u2 * (1.0f / 128.0f) - meanA * meanA, 0.0f) + 1e-5f);
        float meanB = v1 * (1.0f / 128.0f);
        float invB  = rsqrtf(fmaxf(v2 * (1.0f / 128.0f) - meanB * meanB, 0.0f) + 1e-5f);

        int eA = base + rg * 16 + gid, eB = eA + 8;
        int colb = 32 * w + 8 * tig;
        if (eA < E) {
            float4 lo, hi;
            lo.x = (C[0][0] - meanA) * invA * gg2[0].x + bt2[0].x;
            lo.y = (C[0][1] - meanA) * invA * gg2[0].y + bt2[0].y;
            lo.z = (C[1][0] - meanA) * invA * gg2[1].x + bt2[1].x;
            lo.w = (C[1][1] - meanA) * invA * gg2[1].y + bt2[1].y;
            hi.x = (C[2][0] - meanA) * invA * gg2[2].x + bt2[2].x;
            hi.y = (C[2][1] - meanA) * invA * gg2[2].y + bt2[2].y;
            hi.z = (C[3][0] - meanA) * invA * gg2[3].x + bt2[3].x;
            hi.w = (C[3][1] - meanA) * invA * gg2[3].y + bt2[3].y;
            float* dst = hE + (size_t)eA * 128 + colb;
            __stcs(reinterpret_cast<float4*>(dst),     lo);
            __stcs(reinterpret_cast<float4*>(dst + 4), hi);
        }
        if (eB < E) {
            float4 lo, hi;
            lo.x = (C[0][2] - meanB) * invB * gg2[0].x + bt2[0].x;
            lo.y = (C[0][3] - meanB) * invB * gg2[0].y + bt2[0].y;
            lo.z = (C[1][2] - meanB) * invB * gg2[1].x + bt2[1].x;
            lo.w = (C[1][3] - meanB) * invB * gg2[1].y + bt2[1].y;
            hi.x = (C[2][2] - meanB) * invB * gg2[2].x + bt2[2].x;
            hi.y = (C[2][3] - meanB) * invB * gg2[2].y + bt2[2].y;
            hi.z = (C[3][2] - meanB) * invB * gg2[3].x + bt2[3].x;
            hi.w = (C[3][3] - meanB) * invB * gg2[3].y + bt2[3].y;
            float* dst = hE + (size_t)eB * 128 + colb;
            __stcs(reinterpret_cast<float4*>(dst),     lo);
            __stcs(reinterpret_cast<float4*>(dst + 4), hi);
        }
    }
}

// ---------------------------------------------------------------------------
extern "C" void kernel_launch(void* const* d_in, const int* in_sizes, int n_in,
                              void* d_out, int out_size)
{
    const float* X    = (const float*)d_in[0];
    const int*   bat  = (const int*)d_in[1];
    const int*   ei   = (const int*)d_in[2];
    const float* Wn   = (const float*)d_in[3];
    const float* bn   = (const float*)d_in[4];
    const float* gn   = (const float*)d_in[5];
    const float* btn  = (const float*)d_in[6];
    const float* We   = (const float*)d_in[7];
    const float* be   = (const float*)d_in[8];
    const float* ge   = (const float*)d_in[9];
    const float* bte  = (const float*)d_in[10];

    int N = in_sizes[0] / 3;
    int E = in_sizes[2] / 2;

    float* hV = (float*)d_out;
    float* hE = hV + (size_t)N * 128;

    k_node<<<(N + 255) / 256, 256>>>(X, bat, N, Wn, bn, gn, btn, We, be, hV);
    k_edge_fused<<<(E + 127) / 128, 128>>>(ei, E, ge, bte, hE);
}